// round 1
// baseline (speedup 1.0000x reference)
#include <cuda_runtime.h>
#include <math.h>

#define LRDIM 512
#define HRDIM 2048
#define NNODE 4096
#define NHEADS 4
#define CH 512

// ---------------- scratch (device globals: no allocations allowed) ----------
__device__ float g_q[(size_t)NNODE * HRDIM];
__device__ float g_k[(size_t)NNODE * HRDIM];
__device__ float g_v[(size_t)NNODE * HRDIM];
__device__ float g_o[(size_t)NNODE * HRDIM];     // skip, then skip+attn, then gn (in-place)
__device__ float g_scores[(size_t)NNODE * NNODE]; // reused per head (stream-ordered)
__device__ float g_sum[HRDIM];
__device__ float g_sqsum[HRDIM];
__device__ float g_normsq[HRDIM];
__device__ float g_alpha[HRDIM];
__device__ float g_beta[HRDIM];

// ---------------- GEMM: 128x128x16 tiles, 256 threads, 8x8 per thread -------
// AMODE 0: A[k*lda + m] (K-major outer); AMODE 1: A[m*lda + k] (row-major)
// BMODE 0: B[k*ldb + n]; BMODE 1: B[n*ldb + k]
// EPI 0: +bias[n]   EPI 1: *scale   EPI 2: += C   EPI 3: gram (normalize+relu)
constexpr int BM = 128, BN = 128, BK = 16, TM = 8, TN = 8;

template <int AMODE, int BMODE, int EPI>
__global__ __launch_bounds__(256)
void gemm_kernel(const float* __restrict__ A, const float* __restrict__ B,
                 float* __restrict__ C, int K, int lda, int ldb, int ldc,
                 const float* __restrict__ p1, float scale) {
    __shared__ float As[BK][BM + 4];
    __shared__ float Bs[BK][BN + 4];
    const int tid = threadIdx.x;
    const int tx = tid & 15, ty = tid >> 4;
    const int m0 = blockIdx.y * BM;
    const int n0 = blockIdx.x * BN;

    float acc[TM][TN];
#pragma unroll
    for (int i = 0; i < TM; i++)
#pragma unroll
        for (int j = 0; j < TN; j++) acc[i][j] = 0.f;

    for (int k0 = 0; k0 < K; k0 += BK) {
        // ---- load A tile ----
        if (AMODE == 0) {
#pragma unroll
            for (int r = 0; r < 2; r++) {
                int v = tid + r * 256;          // 512 float4s = 128x16
                int kk = v >> 5, mv = v & 31;
                float4 f = *reinterpret_cast<const float4*>(
                    A + (size_t)(k0 + kk) * lda + m0 + mv * 4);
                *reinterpret_cast<float4*>(&As[kk][mv * 4]) = f;
            }
        } else {
#pragma unroll
            for (int r = 0; r < 2; r++) {
                int v = tid + r * 256;
                int mm = v >> 2, kv = v & 3;
                float4 f = *reinterpret_cast<const float4*>(
                    A + (size_t)(m0 + mm) * lda + k0 + kv * 4);
                As[kv * 4 + 0][mm] = f.x;
                As[kv * 4 + 1][mm] = f.y;
                As[kv * 4 + 2][mm] = f.z;
                As[kv * 4 + 3][mm] = f.w;
            }
        }
        // ---- load B tile ----
        if (BMODE == 0) {
#pragma unroll
            for (int r = 0; r < 2; r++) {
                int v = tid + r * 256;
                int kk = v >> 5, nv = v & 31;
                float4 f = *reinterpret_cast<const float4*>(
                    B + (size_t)(k0 + kk) * ldb + n0 + nv * 4);
                *reinterpret_cast<float4*>(&Bs[kk][nv * 4]) = f;
            }
        } else {
#pragma unroll
            for (int r = 0; r < 2; r++) {
                int v = tid + r * 256;
                int nn = v >> 2, kv = v & 3;
                float4 f = *reinterpret_cast<const float4*>(
                    B + (size_t)(n0 + nn) * ldb + k0 + kv * 4);
                Bs[kv * 4 + 0][nn] = f.x;
                Bs[kv * 4 + 1][nn] = f.y;
                Bs[kv * 4 + 2][nn] = f.z;
                Bs[kv * 4 + 3][nn] = f.w;
            }
        }
        __syncthreads();

#pragma unroll
        for (int kk = 0; kk < BK; kk++) {
            float ra[TM], rb[TN];
            *reinterpret_cast<float4*>(&ra[0]) =
                *reinterpret_cast<const float4*>(&As[kk][ty * TM]);
            *reinterpret_cast<float4*>(&ra[4]) =
                *reinterpret_cast<const float4*>(&As[kk][ty * TM + 4]);
            *reinterpret_cast<float4*>(&rb[0]) =
                *reinterpret_cast<const float4*>(&Bs[kk][tx * TN]);
            *reinterpret_cast<float4*>(&rb[4]) =
                *reinterpret_cast<const float4*>(&Bs[kk][tx * TN + 4]);
#pragma unroll
            for (int i = 0; i < TM; i++)
#pragma unroll
                for (int j = 0; j < TN; j++)
                    acc[i][j] = fmaf(ra[i], rb[j], acc[i][j]);
        }
        __syncthreads();
    }

#pragma unroll
    for (int i = 0; i < TM; i++) {
        int m = m0 + ty * TM + i;
#pragma unroll
        for (int j = 0; j < TN; j++) {
            int n = n0 + tx * TN + j;
            float r = acc[i][j];
            size_t idx = (size_t)m * ldc + n;
            if (EPI == 0) r += p1[n];
            else if (EPI == 1) r *= scale;
            else if (EPI == 2) r += C[idx];
            else if (EPI == 3) {
                r = r * rsqrtf(p1[m]) * rsqrtf(p1[n]);
                r = fmaxf(r, 0.f);
            }
            C[idx] = r;
        }
    }
}

// ---------------- row softmax over 4096-wide rows ---------------------------
__global__ __launch_bounds__(256)
void softmax_rows(float* __restrict__ S, int N) {
    float* row = S + (size_t)blockIdx.x * N;
    const int tid = threadIdx.x;
    __shared__ float red[256];

    float mx = -3.4e38f;
    for (int i = tid; i < N; i += 256) mx = fmaxf(mx, row[i]);
    red[tid] = mx;
    __syncthreads();
    for (int s = 128; s > 0; s >>= 1) {
        if (tid < s) red[tid] = fmaxf(red[tid], red[tid + s]);
        __syncthreads();
    }
    mx = red[0];
    __syncthreads();

    float sum = 0.f;
    for (int i = tid; i < N; i += 256) {
        float e = __expf(row[i] - mx);
        row[i] = e;
        sum += e;
    }
    red[tid] = sum;
    __syncthreads();
    for (int s = 128; s > 0; s >>= 1) {
        if (tid < s) red[tid] += red[tid + s];
        __syncthreads();
    }
    float inv = 1.f / red[0];
    for (int i = tid; i < N; i += 256) row[i] *= inv;
}

// ---------------- per-channel statistics over nodes -------------------------
__global__ void zero_stats() {
    int i = blockIdx.x * 256 + threadIdx.x;
    if (i < HRDIM) { g_sum[i] = 0.f; g_sqsum[i] = 0.f; g_normsq[i] = 0.f; }
}

// grid (HRDIM/256, NNODE/512), block 256; thread owns one channel
__global__ __launch_bounds__(256)
void stats_kernel(const float* __restrict__ X) {
    int ch = blockIdx.x * 256 + threadIdx.x;
    int n0 = blockIdx.y * 512;
    float s = 0.f, s2 = 0.f;
    for (int n = n0; n < n0 + 512; n++) {
        float v = X[(size_t)n * HRDIM + ch];
        s += v;
        s2 += v * v;
    }
    atomicAdd(&g_sum[ch], s);
    atomicAdd(&g_sqsum[ch], s2);
}

__global__ void finalize_stats(const float* __restrict__ gw,
                               const float* __restrict__ gb,
                               const float* __restrict__ gms) {
    int j = blockIdx.x * 256 + threadIdx.x;
    if (j >= HRDIM) return;
    float m = g_sum[j] * (1.f / NNODE);
    float e2 = g_sqsum[j] * (1.f / NNODE);
    float s = gms[j];
    // var = E[(o - s*m)^2] = E[o^2] - 2*s*m*E[o] + s^2*m^2
    float var = e2 - 2.f * s * m * m + s * s * m * m;
    float a = rsqrtf(var + 1e-5f) * gw[j];
    g_alpha[j] = a;
    g_beta[j] = gb[j] - s * m * a;
}

// in-place normalize + accumulate column squared-norms
__global__ __launch_bounds__(256)
void normalize_kernel(float* __restrict__ X) {
    int ch = blockIdx.x * 256 + threadIdx.x;
    int n0 = blockIdx.y * 512;
    float a = g_alpha[ch], b = g_beta[ch];
    float ns = 0.f;
    for (int n = n0; n < n0 + 512; n++) {
        size_t idx = (size_t)n * HRDIM + ch;
        float g = X[idx] * a + b;
        X[idx] = g;
        ns += g * g;
    }
    atomicAdd(&g_normsq[ch], ns);
}

// ---------------- launch ----------------------------------------------------
extern "C" void kernel_launch(void* const* d_in, const int* in_sizes, int n_in,
                              void* d_out, int out_size) {
    const float* lr_x = (const float*)d_in[0];
    const float* Wq = (const float*)d_in[1];
    const float* bq = (const float*)d_in[2];
    const float* Wk = (const float*)d_in[3];
    const float* bk = (const float*)d_in[4];
    const float* Wv = (const float*)d_in[5];
    const float* bv = (const float*)d_in[6];
    const float* Ws = (const float*)d_in[7];
    const float* bs = (const float*)d_in[8];
    const float* gw = (const float*)d_in[9];
    const float* gb = (const float*)d_in[10];
    const float* gms = (const float*)d_in[11];
    float* out = (float*)d_out;

    float *q, *k, *v, *o, *sc, *nrm;
    cudaGetSymbolAddress((void**)&q, g_q);
    cudaGetSymbolAddress((void**)&k, g_k);
    cudaGetSymbolAddress((void**)&v, g_v);
    cudaGetSymbolAddress((void**)&o, g_o);
    cudaGetSymbolAddress((void**)&sc, g_scores);
    cudaGetSymbolAddress((void**)&nrm, g_normsq);

    zero_stats<<<(HRDIM + 255) / 256, 256>>>();

    // Q, K, V, skip projections: C[m,n] = sum_k lr_x[k,m] * W[k,n] + b[n]
    dim3 gProj(HRDIM / BN, NNODE / BM);
    gemm_kernel<0, 0, 0><<<gProj, 256>>>(lr_x, Wq, q, LRDIM, NNODE, HRDIM, HRDIM, bq, 0.f);
    gemm_kernel<0, 0, 0><<<gProj, 256>>>(lr_x, Wk, k, LRDIM, NNODE, HRDIM, HRDIM, bk, 0.f);
    gemm_kernel<0, 0, 0><<<gProj, 256>>>(lr_x, Wv, v, LRDIM, NNODE, HRDIM, HRDIM, bv, 0.f);
    gemm_kernel<0, 0, 0><<<gProj, 256>>>(lr_x, Ws, o, LRDIM, NNODE, HRDIM, HRDIM, bs, 0.f);

    const float scale = 1.f / sqrtf((float)CH);
    dim3 gScore(NNODE / BN, NNODE / BM);
    dim3 gAV(CH / BN, NNODE / BM);
    for (int h = 0; h < NHEADS; h++) {
        const float* qh = q + h * CH;
        const float* kh = k + h * CH;
        const float* vh = v + h * CH;
        // scores = (Qh @ Kh^T) * scale : A row-major [N,K], B row-major-along-K
        gemm_kernel<1, 1, 1><<<gScore, 256>>>(qh, kh, sc, CH, HRDIM, HRDIM, NNODE,
                                              nullptr, scale);
        softmax_rows<<<NNODE, 256>>>(sc, NNODE);
        // o[:, h*CH:(h+1)*CH] += attn @ Vh
        gemm_kernel<1, 0, 2><<<gAV, 256>>>(sc, vh, o + h * CH, NNODE, NNODE, HRDIM,
                                           HRDIM, nullptr, 0.f);
    }

    dim3 gStat(HRDIM / 256, NNODE / 512);
    stats_kernel<<<gStat, 256>>>(o);
    finalize_stats<<<(HRDIM + 255) / 256, 256>>>(gw, gb, gms);
    normalize_kernel<<<gStat, 256>>>(o);

    // gram: G[i,j] = relu( sum_n gn[n,i]*gn[n,j] / (||i|| * ||j||) )
    dim3 gGram(HRDIM / BN, HRDIM / BM);
    gemm_kernel<0, 0, 3><<<gGram, 256>>>(o, o, out, NNODE, HRDIM, HRDIM, HRDIM,
                                         nrm, 0.f);
}

// round 7
// speedup vs baseline: 2.9883x; 2.9883x over previous
#include <cuda_runtime.h>
#include <math.h>
#include <stdint.h>

#define LRDIM 512
#define HRDIM 2048
#define NNODE 4096
#define NHEADS 4
#define CH 512

// ---------------- scratch (device globals; no allocation allowed) -----------
__device__ float g_xT[(size_t)NNODE * LRDIM];      // lr_x transposed, tf32-rounded
__device__ float g_w4[4][(size_t)LRDIM * HRDIM];   // Wq,Wk,Wv,Ws tf32-rounded
__device__ float g_q[(size_t)NNODE * HRDIM];
__device__ float g_k[(size_t)NNODE * HRDIM];
__device__ float g_v[(size_t)NNODE * HRDIM];
__device__ float g_o[(size_t)NNODE * HRDIM];
__device__ float g_scores[(size_t)NNODE * NNODE];  // scores -> attn in place
__device__ float g_gn[(size_t)NNODE * HRDIM];
__device__ float g_gnT[(size_t)HRDIM * NNODE];
__device__ float g_sum[HRDIM];
__device__ float g_sqsum[HRDIM];
__device__ float g_normsq[HRDIM];
__device__ float g_alpha[HRDIM];
__device__ float g_beta[HRDIM];

// ---------------- PTX helpers ------------------------------------------------
__device__ __forceinline__ uint32_t smem_u32(const void* p) {
    return (uint32_t)__cvta_generic_to_shared(p);
}
__device__ __forceinline__ void cp16(void* s, const void* g) {
    asm volatile("cp.async.cg.shared.global [%0], [%1], 16;\n"
                 :: "r"(smem_u32(s)), "l"(g));
}
__device__ __forceinline__ void cp_commit() {
    asm volatile("cp.async.commit_group;\n");
}
template <int N> __device__ __forceinline__ void cp_wait() {
    asm volatile("cp.async.wait_group %0;\n" :: "n"(N));
}
__device__ __forceinline__ float rtf32(float x) {
    uint32_t u;
    asm("cvt.rna.tf32.f32 %0, %1;\n" : "=r"(u) : "f"(x));
    return __uint_as_float(u);
}
__device__ __forceinline__ void mma1688(float* c, const uint32_t* a, const uint32_t* b) {
    asm volatile(
        "mma.sync.aligned.m16n8k8.row.col.f32.tf32.tf32.f32 "
        "{%0,%1,%2,%3}, {%4,%5,%6,%7}, {%8,%9}, {%0,%1,%2,%3};\n"
        : "+f"(c[0]), "+f"(c[1]), "+f"(c[2]), "+f"(c[3])
        : "r"(a[0]), "r"(a[1]), "r"(a[2]), "r"(a[3]), "r"(b[0]), "r"(b[1]));
}

// ---------------- tf32 tensor-core GEMM -------------------------------------
// C[M,N] = A[M,K] (row-major fp32, lda) * B
// BMODE 0 ("NN"): B row-major [K][N] (ldb)
// BMODE 1 ("NT"): B row-major [N][K] (ldb)  -> computes A * B^T
// EPI 0: +bias, tf32-round -> C     EPI 1: +bias -> C
// EPI 2: *scale -> C                EPI 3: C += acc
// EPI 4: gram normalize + relu -> C (p1 = squared norms)
template <int BMODE, int EPI>
__global__ __launch_bounds__(256)
void tf32_gemm(const float* __restrict__ A, const float* __restrict__ B,
               int K, int lda, int ldb,
               float* __restrict__ C, int ldc,
               const float* __restrict__ p1, float scale) {
    constexpr int BM = 128, BN = 128, BK = 16;
    constexpr int BSR = (BMODE == 0) ? BK : BN;
    constexpr int BSC = (BMODE == 0) ? (BN + 8) : (BK + 4);
    __shared__ float As[2][BM][BK + 4];   // stride 20 floats: conflict-free
    __shared__ float Bs[2][BSR][BSC];     // NN stride 136, NT stride 20: conflict-free

    const int tid = threadIdx.x, lane = tid & 31, warp = tid >> 5;
    const int wm = warp >> 2, wn = warp & 3;        // 2 x 4 warp grid, 64x32 warp tile
    const int m0 = blockIdx.y * BM, n0 = blockIdx.x * BN;

    float acc[4][4][4];
#pragma unroll
    for (int i = 0; i < 4; i++)
#pragma unroll
        for (int j = 0; j < 4; j++)
#pragma unroll
            for (int l = 0; l < 4; l++) acc[i][j][l] = 0.f;

    auto loadA = [&](int buf, int k0) {
#pragma unroll
        for (int r = 0; r < 2; r++) {
            int c = tid + 256 * r;               // 512 float4s = 128 x 16 floats
            int row = c >> 2, ch = c & 3;
            cp16(&As[buf][row][ch * 4], A + (size_t)(m0 + row) * lda + k0 + ch * 4);
        }
    };
    auto loadB = [&](int buf, int k0) {
        if (BMODE == 0) {
#pragma unroll
            for (int r = 0; r < 2; r++) {
                int c = tid + 256 * r;           // 16 rows x 32 chunks
                int row = c >> 5, ch = c & 31;
                cp16(&Bs[buf][row][ch * 4], B + (size_t)(k0 + row) * ldb + n0 + ch * 4);
            }
        } else {
#pragma unroll
            for (int r = 0; r < 2; r++) {
                int c = tid + 256 * r;           // 128 rows x 4 chunks
                int row = c >> 2, ch = c & 3;
                cp16(&Bs[buf][row][ch * 4], B + (size_t)(n0 + row) * ldb + k0 + ch * 4);
            }
        }
    };

    loadA(0, 0); loadB(0, 0); cp_commit();
    int buf = 0;
    for (int k0 = 0; k0 < K; k0 += BK) {
        bool has_next = (k0 + BK < K);
        if (has_next) { loadA(buf ^ 1, k0 + BK); loadB(buf ^ 1, k0 + BK); cp_commit(); }
        if (has_next) cp_wait<1>(); else cp_wait<0>();
        __syncthreads();

#pragma unroll
        for (int kk = 0; kk < 2; kk++) {
            const int ar = lane >> 2;           // group id = row within 8
            const int ak = kk * 8 + (lane & 3); // k column
            uint32_t a[4][4], b[4][2];
#pragma unroll
            for (int mi = 0; mi < 4; mi++) {
                const float* p = &As[buf][wm * 64 + mi * 16 + ar][ak];
                a[mi][0] = __float_as_uint(p[0]);
                a[mi][1] = __float_as_uint(p[8 * (BK + 4)]);
                a[mi][2] = __float_as_uint(p[4]);
                a[mi][3] = __float_as_uint(p[8 * (BK + 4) + 4]);
            }
            if (BMODE == 0) {
#pragma unroll
                for (int ni = 0; ni < 4; ni++) {
                    int col = wn * 32 + ni * 8 + (lane >> 2);
                    b[ni][0] = __float_as_uint(Bs[buf][ak][col]);
                    b[ni][1] = __float_as_uint(Bs[buf][ak + 4][col]);
                }
            } else {
#pragma unroll
                for (int ni = 0; ni < 4; ni++) {
                    int row = wn * 32 + ni * 8 + (lane >> 2);
                    b[ni][0] = __float_as_uint(Bs[buf][row][ak]);
                    b[ni][1] = __float_as_uint(Bs[buf][row][ak + 4]);
                }
            }
#pragma unroll
            for (int mi = 0; mi < 4; mi++)
#pragma unroll
                for (int ni = 0; ni < 4; ni++)
                    mma1688(acc[mi][ni], a[mi], b[ni]);
        }
        __syncthreads();
        buf ^= 1;
    }

    // epilogue: c0,c1 -> (row=group, col=2t,2t+1); c2,c3 -> row+8
    const int rb = lane >> 2, cb = (lane & 3) * 2;
#pragma unroll
    for (int mi = 0; mi < 4; mi++) {
#pragma unroll
        for (int half = 0; half < 2; half++) {
            int r = m0 + wm * 64 + mi * 16 + rb + half * 8;
            float rs_r = 0.f;
            if (EPI == 4) rs_r = rsqrtf(p1[r]);
#pragma unroll
            for (int ni = 0; ni < 4; ni++) {
                int col = n0 + wn * 32 + ni * 8 + cb;
                float v0 = acc[mi][ni][half * 2 + 0];
                float v1 = acc[mi][ni][half * 2 + 1];
                size_t idx = (size_t)r * ldc + col;
                if (EPI == 0) {
                    v0 = rtf32(v0 + p1[col]); v1 = rtf32(v1 + p1[col + 1]);
                    *(float2*)(C + idx) = make_float2(v0, v1);
                } else if (EPI == 1) {
                    *(float2*)(C + idx) = make_float2(v0 + p1[col], v1 + p1[col + 1]);
                } else if (EPI == 2) {
                    *(float2*)(C + idx) = make_float2(v0 * scale, v1 * scale);
                } else if (EPI == 3) {
                    float2 old = *(float2*)(C + idx);
                    *(float2*)(C + idx) = make_float2(old.x + v0, old.y + v1);
                } else {
                    v0 = fmaxf(v0 * rs_r * rsqrtf(p1[col]), 0.f);
                    v1 = fmaxf(v1 * rs_r * rsqrtf(p1[col + 1]), 0.f);
                    *(float2*)(C + idx) = make_float2(v0, v1);
                }
            }
        }
    }
}

// ---------------- prep kernels ------------------------------------------------
__global__ void round_copy(const float* __restrict__ x, float* __restrict__ y, int n) {
    int i = blockIdx.x * 256 + threadIdx.x;
    if (i < n) y[i] = rtf32(x[i]);
}

// lr_x [LR][N] -> xT [N][LR], tf32-rounded
__global__ void tconv_x_kernel(const float* __restrict__ X, float* __restrict__ Y) {
    __shared__ float t[32][33];
    int n0 = blockIdx.x * 32, k0 = blockIdx.y * 32;
    int tx = threadIdx.x, ty = threadIdx.y;
#pragma unroll
    for (int r = 0; r < 32; r += 8)
        t[ty + r][tx] = X[(size_t)(k0 + ty + r) * NNODE + n0 + tx];
    __syncthreads();
#pragma unroll
    for (int r = 0; r < 32; r += 8)
        Y[(size_t)(n0 + ty + r) * LRDIM + k0 + tx] = rtf32(t[tx][ty + r]);
}

// gn [N][HR] -> gnT [HR][N]
__global__ void tpose_kernel(const float* __restrict__ X, float* __restrict__ Y) {
    __shared__ float t[32][33];
    int c0 = blockIdx.x * 32, n0 = blockIdx.y * 32;
    int tx = threadIdx.x, ty = threadIdx.y;
#pragma unroll
    for (int r = 0; r < 32; r += 8)
        t[ty + r][tx] = X[(size_t)(n0 + ty + r) * HRDIM + c0 + tx];
    __syncthreads();
#pragma unroll
    for (int r = 0; r < 32; r += 8)
        Y[(size_t)(c0 + ty + r) * NNODE + n0 + tx] = t[tx][ty + r];
}

// ---------------- softmax: in-place fp32, tf32-rounded output ----------------
__global__ __launch_bounds__(256)
void softmax_rows(float* __restrict__ S) {
    int row = blockIdx.x, tid = threadIdx.x;
    float2* r2 = (float2*)(S + (size_t)row * NNODE);
    __shared__ float red[256];

    float2 v[8];
    float mx = -3.4e38f;
#pragma unroll
    for (int j = 0; j < 8; j++) {
        v[j] = r2[tid + j * 256];
        mx = fmaxf(mx, fmaxf(v[j].x, v[j].y));
    }
    red[tid] = mx;
    __syncthreads();
    for (int s = 128; s > 0; s >>= 1) {
        if (tid < s) red[tid] = fmaxf(red[tid], red[tid + s]);
        __syncthreads();
    }
    mx = red[0];
    __syncthreads();

    float sum = 0.f;
#pragma unroll
    for (int j = 0; j < 8; j++) {
        v[j].x = __expf(v[j].x - mx);
        v[j].y = __expf(v[j].y - mx);
        sum += v[j].x + v[j].y;
    }
    red[tid] = sum;
    __syncthreads();
    for (int s = 128; s > 0; s >>= 1) {
        if (tid < s) red[tid] += red[tid + s];
        __syncthreads();
    }
    float inv = 1.f / red[0];
#pragma unroll
    for (int j = 0; j < 8; j++)
        r2[tid + j * 256] = make_float2(rtf32(v[j].x * inv), rtf32(v[j].y * inv));
}

// ---------------- GraphNorm statistics ---------------------------------------
__global__ void zero_stats() {
    int i = blockIdx.x * 256 + threadIdx.x;
    if (i < HRDIM) { g_sum[i] = 0.f; g_sqsum[i] = 0.f; g_normsq[i] = 0.f; }
}

__global__ __launch_bounds__(256)
void stats_kernel(const float* __restrict__ X) {
    int ch = blockIdx.x * 256 + threadIdx.x;
    int n0 = blockIdx.y * 512;
    float s = 0.f, s2 = 0.f;
    for (int n = n0; n < n0 + 512; n++) {
        float v = X[(size_t)n * HRDIM + ch];
        s += v;
        s2 += v * v;
    }
    atomicAdd(&g_sum[ch], s);
    atomicAdd(&g_sqsum[ch], s2);
}

__global__ void finalize_stats(const float* __restrict__ gw,
                               const float* __restrict__ gb,
                               const float* __restrict__ gms) {
    int j = blockIdx.x * 256 + threadIdx.x;
    if (j >= HRDIM) return;
    float m = g_sum[j] * (1.f / NNODE);
    float e2 = g_sqsum[j] * (1.f / NNODE);
    float s = gms[j];
    // var = E[o^2] - 2 s m E[o] + s^2 m^2
    float var = e2 - 2.f * s * m * m + s * s * m * m;
    float a = rsqrtf(var + 1e-5f) * gw[j];
    g_alpha[j] = a;
    g_beta[j] = gb[j] - s * m * a;
}

// normalize o -> gn (tf32-rounded), accumulate per-channel squared norms
__global__ __launch_bounds__(256)
void normalize_kernel(const float* __restrict__ X, float* __restrict__ Y) {
    int ch = blockIdx.x * 256 + threadIdx.x;
    int n0 = blockIdx.y * 512;
    float a = g_alpha[ch], b = g_beta[ch];
    float ns = 0.f;
    for (int n = n0; n < n0 + 512; n++) {
        size_t idx = (size_t)n * HRDIM + ch;
        float g = rtf32(X[idx] * a + b);
        Y[idx] = g;
        ns += g * g;
    }
    atomicAdd(&g_normsq[ch], ns);
}

// ---------------- launch ------------------------------------------------------
extern "C" void kernel_launch(void* const* d_in, const int* in_sizes, int n_in,
                              void* d_out, int out_size) {
    const float* lr_x = (const float*)d_in[0];
    const float* Wq = (const float*)d_in[1];
    const float* bq = (const float*)d_in[2];
    const float* Wk = (const float*)d_in[3];
    const float* bk = (const float*)d_in[4];
    const float* Wv = (const float*)d_in[5];
    const float* bv = (const float*)d_in[6];
    const float* Ws = (const float*)d_in[7];
    const float* bs = (const float*)d_in[8];
    const float* gw = (const float*)d_in[9];
    const float* gb = (const float*)d_in[10];
    const float* gms = (const float*)d_in[11];
    float* out = (float*)d_out;

    float *xT, *w4, *q, *k, *v, *o, *sc, *gn, *gnT, *nrm;
    cudaGetSymbolAddress((void**)&xT, g_xT);
    cudaGetSymbolAddress((void**)&w4, g_w4);
    cudaGetSymbolAddress((void**)&q, g_q);
    cudaGetSymbolAddress((void**)&k, g_k);
    cudaGetSymbolAddress((void**)&v, g_v);
    cudaGetSymbolAddress((void**)&o, g_o);
    cudaGetSymbolAddress((void**)&sc, g_scores);
    cudaGetSymbolAddress((void**)&gn, g_gn);
    cudaGetSymbolAddress((void**)&gnT, g_gnT);
    cudaGetSymbolAddress((void**)&nrm, g_normsq);

    const size_t WN = (size_t)LRDIM * HRDIM;
    float* wq = w4;
    float* wk = w4 + WN;
    float* wv = w4 + 2 * WN;
    float* ws = w4 + 3 * WN;

    zero_stats<<<(HRDIM + 255) / 256, 256>>>();

    // prep: transpose+round x, round weights
    tconv_x_kernel<<<dim3(NNODE / 32, LRDIM / 32), dim3(32, 8)>>>(lr_x, xT);
    round_copy<<<(WN + 255) / 256, 256>>>(Wq, wq, WN);
    round_copy<<<(WN + 255) / 256, 256>>>(Wk, wk, WN);
    round_copy<<<(WN + 255) / 256, 256>>>(Wv, wv, WN);
    round_copy<<<(WN + 255) / 256, 256>>>(Ws, ws, WN);

    // projections: [4096,512] x [512,2048] (NN)
    dim3 gProj(HRDIM / 128, NNODE / 128);
    tf32_gemm<0, 0><<<gProj, 256>>>(xT, wq, LRDIM, LRDIM, HRDIM, q, HRDIM, bq, 0.f);
    tf32_gemm<0, 0><<<gProj, 256>>>(xT, wk, LRDIM, LRDIM, HRDIM, k, HRDIM, bk, 0.f);
    tf32_gemm<0, 0><<<gProj, 256>>>(xT, wv, LRDIM, LRDIM, HRDIM, v, HRDIM, bv, 0.f);
    tf32_gemm<0, 1><<<gProj, 256>>>(xT, ws, LRDIM, LRDIM, HRDIM, o, HRDIM, bs, 0.f);

    const float scale = 1.f / sqrtf((float)CH);
    dim3 gScore(NNODE / 128, NNODE / 128);
    dim3 gAV(CH / 128, NNODE / 128);
    for (int h = 0; h < NHEADS; h++) {
        // scores = scale * Qh @ Kh^T  (NT)
        tf32_gemm<1, 2><<<gScore, 256>>>(q + h * CH, k + h * CH, CH, HRDIM, HRDIM,
                                         sc, NNODE, nullptr, scale);
        softmax_rows<<<NNODE, 256>>>(sc);
        // o[:, hCH:(h+1)CH] += attn @ Vh  (NN)
        tf32_gemm<0, 3><<<gAV, 256>>>(sc, v + h * CH, NNODE, NNODE, HRDIM,
                                      o + h * CH, HRDIM, nullptr, 0.f);
    }

    dim3 gStat(HRDIM / 256, NNODE / 512);
    stats_kernel<<<gStat, 256>>>(o);
    finalize_stats<<<(HRDIM + 255) / 256, 256>>>(gw, gb, gms);
    normalize_kernel<<<gStat, 256>>>(o, gn);
    tpose_kernel<<<dim3(HRDIM / 32, NNODE / 32), dim3(32, 8)>>>(gn, gnT);

    // gram: [2048,4096] x [4096,2048] (NN), normalized + relu
    dim3 gGram(HRDIM / 128, HRDIM / 128);
    tf32_gemm<0, 4><<<gGram, 256>>>(gnT, gn, NNODE, NNODE, HRDIM,
                                    out, HRDIM, nrm, 0.f);
}

// round 9
// speedup vs baseline: 3.4529x; 1.1555x over previous
#include <cuda_runtime.h>
#include <math.h>
#include <stdint.h>

#define LRDIM 512
#define HRDIM 2048
#define NNODE 4096
#define NHEADS 4
#define CH 512

// ---------------- scratch (device globals; no allocation allowed) -----------
__device__ float g_xT[(size_t)NNODE * LRDIM];      // lr_x transposed, tf32-rounded
__device__ float g_w4[4][(size_t)LRDIM * HRDIM];   // Wq,Wk,Wv,Ws tf32-rounded
__device__ float g_q[(size_t)NNODE * HRDIM];
__device__ float g_k[(size_t)NNODE * HRDIM];
__device__ float g_v[(size_t)NNODE * HRDIM];
__device__ float g_o[(size_t)NNODE * HRDIM];
__device__ float g_scores[(size_t)NHEADS * NNODE * NNODE]; // all heads batched
__device__ float g_gn[(size_t)NNODE * HRDIM];
__device__ float g_gnT[(size_t)HRDIM * NNODE];
__device__ float g_sum[HRDIM];
__device__ float g_sqsum[HRDIM];
__device__ float g_normsq[HRDIM];
__device__ float g_alpha[HRDIM];
__device__ float g_beta[HRDIM];

// ---------------- PTX helpers ------------------------------------------------
__device__ __forceinline__ uint32_t smem_u32(const void* p) {
    return (uint32_t)__cvta_generic_to_shared(p);
}
__device__ __forceinline__ void cp16(void* s, const void* g) {
    asm volatile("cp.async.cg.shared.global [%0], [%1], 16;\n"
                 :: "r"(smem_u32(s)), "l"(g));
}
__device__ __forceinline__ void cp_commit() {
    asm volatile("cp.async.commit_group;\n");
}
template <int N> __device__ __forceinline__ void cp_wait() {
    asm volatile("cp.async.wait_group %0;\n" :: "n"(N));
}
__device__ __forceinline__ float rtf32(float x) {
    uint32_t u;
    asm("cvt.rna.tf32.f32 %0, %1;\n" : "=r"(u) : "f"(x));
    return __uint_as_float(u);
}
__device__ __forceinline__ void mma1688(float* c, const uint32_t* a, const uint32_t* b) {
    asm volatile(
        "mma.sync.aligned.m16n8k8.row.col.f32.tf32.tf32.f32 "
        "{%0,%1,%2,%3}, {%4,%5,%6,%7}, {%8,%9}, {%0,%1,%2,%3};\n"
        : "+f"(c[0]), "+f"(c[1]), "+f"(c[2]), "+f"(c[3])
        : "r"(a[0]), "r"(a[1]), "r"(a[2]), "r"(a[3]), "r"(b[0]), "r"(b[1]));
}

// ---------------- tf32 tensor-core GEMM -------------------------------------
// 128x128x16 CTA tile, 128 threads (4 warps), 64x64 warp tile.
// C[M,N] = A[M,K] (row-major fp32, lda) * B ; blockIdx.z batches heads via
// aHS/bHS/cHS element strides.
// BMODE 0 ("NN"): B row-major [K][N] (ldb)
// BMODE 1 ("NT"): B row-major [N][K] (ldb)  -> computes A * B^T
// EPI 0: +bias, tf32-round -> C     EPI 1: +bias -> C
// EPI 2: *scale -> C                EPI 3: C += acc
// EPI 4: gram normalize + relu -> C (p1 = squared norms)
template <int BMODE, int EPI>
__global__ __launch_bounds__(128)
void tf32_gemm(const float* __restrict__ A, const float* __restrict__ B,
               int K, int lda, int ldb,
               float* __restrict__ C, int ldc,
               const float* __restrict__ p1, float scale,
               size_t aHS, size_t bHS, size_t cHS) {
    constexpr int BM = 128, BN = 128, BK = 16;
    constexpr int BSR = (BMODE == 0) ? BK : BN;
    constexpr int BSC = (BMODE == 0) ? (BN + 8) : (BK + 4);
    __shared__ float As[2][BM][BK + 4];   // stride 20 floats: conflict-free
    __shared__ float Bs[2][BSR][BSC];     // NN stride 136, NT stride 20: conflict-free

    A += (size_t)blockIdx.z * aHS;
    B += (size_t)blockIdx.z * bHS;
    C += (size_t)blockIdx.z * cHS;

    const int tid = threadIdx.x, lane = tid & 31, warp = tid >> 5;
    const int wm = warp >> 1, wn = warp & 1;        // 2 x 2 warp grid, 64x64 warp tile
    const int m0 = blockIdx.y * BM, n0 = blockIdx.x * BN;

    float acc[4][8][4];
#pragma unroll
    for (int i = 0; i < 4; i++)
#pragma unroll
        for (int j = 0; j < 8; j++)
#pragma unroll
            for (int l = 0; l < 4; l++) acc[i][j][l] = 0.f;

    auto loadA = [&](int buf, int k0) {
#pragma unroll
        for (int r = 0; r < 4; r++) {
            int c = tid + 128 * r;               // 512 float4s = 128 x 16 floats
            int row = c >> 2, ch = c & 3;
            cp16(&As[buf][row][ch * 4], A + (size_t)(m0 + row) * lda + k0 + ch * 4);
        }
    };
    auto loadB = [&](int buf, int k0) {
        if (BMODE == 0) {
#pragma unroll
            for (int r = 0; r < 4; r++) {
                int c = tid + 128 * r;           // 16 rows x 32 chunks
                int row = c >> 5, ch = c & 31;
                cp16(&Bs[buf][row][ch * 4], B + (size_t)(k0 + row) * ldb + n0 + ch * 4);
            }
        } else {
#pragma unroll
            for (int r = 0; r < 4; r++) {
                int c = tid + 128 * r;           // 128 rows x 4 chunks
                int row = c >> 2, ch = c & 3;
                cp16(&Bs[buf][row][ch * 4], B + (size_t)(n0 + row) * ldb + k0 + ch * 4);
            }
        }
    };

    loadA(0, 0); loadB(0, 0); cp_commit();
    int buf = 0;
    for (int k0 = 0; k0 < K; k0 += BK) {
        bool has_next = (k0 + BK < K);
        if (has_next) { loadA(buf ^ 1, k0 + BK); loadB(buf ^ 1, k0 + BK); cp_commit(); }
        if (has_next) cp_wait<1>(); else cp_wait<0>();
        __syncthreads();

#pragma unroll
        for (int kk = 0; kk < 2; kk++) {
            const int ar = lane >> 2;           // group id = row within 8
            const int ak = kk * 8 + (lane & 3); // k column
            uint32_t a[4][4], b[8][2];
#pragma unroll
            for (int mi = 0; mi < 4; mi++) {
                const float* p = &As[buf][wm * 64 + mi * 16 + ar][ak];
                a[mi][0] = __float_as_uint(p[0]);
                a[mi][1] = __float_as_uint(p[8 * (BK + 4)]);
                a[mi][2] = __float_as_uint(p[4]);
                a[mi][3] = __float_as_uint(p[8 * (BK + 4) + 4]);
            }
            if (BMODE == 0) {
#pragma unroll
                for (int ni = 0; ni < 8; ni++) {
                    int col = wn * 64 + ni * 8 + (lane >> 2);
                    b[ni][0] = __float_as_uint(Bs[buf][ak][col]);
                    b[ni][1] = __float_as_uint(Bs[buf][ak + 4][col]);
                }
            } else {
#pragma unroll
                for (int ni = 0; ni < 8; ni++) {
                    int row = wn * 64 + ni * 8 + (lane >> 2);
                    b[ni][0] = __float_as_uint(Bs[buf][row][ak]);
                    b[ni][1] = __float_as_uint(Bs[buf][row][ak + 4]);
                }
            }
#pragma unroll
            for (int mi = 0; mi < 4; mi++)
#pragma unroll
                for (int ni = 0; ni < 8; ni++)
                    mma1688(acc[mi][ni], a[mi], b[ni]);
        }
        __syncthreads();
        buf ^= 1;
    }

    // epilogue: c0,c1 -> (row=group, col=2t,2t+1); c2,c3 -> row+8
    const int rb = lane >> 2, cb = (lane & 3) * 2;
#pragma unroll
    for (int mi = 0; mi < 4; mi++) {
#pragma unroll
        for (int half = 0; half < 2; half++) {
            int r = m0 + wm * 64 + mi * 16 + rb + half * 8;
            float rs_r = 0.f;
            if (EPI == 4) rs_r = rsqrtf(p1[r]);
#pragma unroll
            for (int ni = 0; ni < 8; ni++) {
                int col = n0 + wn * 64 + ni * 8 + cb;
                float v0 = acc[mi][ni][half * 2 + 0];
                float v1 = acc[mi][ni][half * 2 + 1];
                size_t idx = (size_t)r * ldc + col;
                if (EPI == 0) {
                    v0 = rtf32(v0 + p1[col]); v1 = rtf32(v1 + p1[col + 1]);
                    *(float2*)(C + idx) = make_float2(v0, v1);
                } else if (EPI == 1) {
                    *(float2*)(C + idx) = make_float2(v0 + p1[col], v1 + p1[col + 1]);
                } else if (EPI == 2) {
                    *(float2*)(C + idx) = make_float2(v0 * scale, v1 * scale);
                } else if (EPI == 3) {
                    float2 old = *(float2*)(C + idx);
                    *(float2*)(C + idx) = make_float2(old.x + v0, old.y + v1);
                } else {
                    v0 = fmaxf(v0 * rs_r * rsqrtf(p1[col]), 0.f);
                    v1 = fmaxf(v1 * rs_r * rsqrtf(p1[col + 1]), 0.f);
                    *(float2*)(C + idx) = make_float2(v0, v1);
                }
            }
        }
    }
}

// ---------------- prep kernels ------------------------------------------------
__global__ void round_copy(const float* __restrict__ x, float* __restrict__ y, int n) {
    int i = blockIdx.x * 256 + threadIdx.x;
    if (i < n) y[i] = rtf32(x[i]);
}

// lr_x [LR][N] -> xT [N][LR], tf32-rounded
__global__ void tconv_x_kernel(const float* __restrict__ X, float* __restrict__ Y) {
    __shared__ float t[32][33];
    int n0 = blockIdx.x * 32, k0 = blockIdx.y * 32;
    int tx = threadIdx.x, ty = threadIdx.y;
#pragma unroll
    for (int r = 0; r < 32; r += 8)
        t[ty + r][tx] = X[(size_t)(k0 + ty + r) * NNODE + n0 + tx];
    __syncthreads();
#pragma unroll
    for (int r = 0; r < 32; r += 8)
        Y[(size_t)(n0 + ty + r) * LRDIM + k0 + tx] = rtf32(t[tx][ty + r]);
}

// gn [N][HR] -> gnT [HR][N]
__global__ void tpose_kernel(const float* __restrict__ X, float* __restrict__ Y) {
    __shared__ float t[32][33];
    int c0 = blockIdx.x * 32, n0 = blockIdx.y * 32;
    int tx = threadIdx.x, ty = threadIdx.y;
#pragma unroll
    for (int r = 0; r < 32; r += 8)
        t[ty + r][tx] = X[(size_t)(n0 + ty + r) * HRDIM + c0 + tx];
    __syncthreads();
#pragma unroll
    for (int r = 0; r < 32; r += 8)
        Y[(size_t)(c0 + ty + r) * NNODE + n0 + tx] = t[tx][ty + r];
}

// ---------------- softmax: in-place fp32, tf32-rounded output ----------------
// grid (NNODE, NHEADS): one block per (row, head)
__global__ __launch_bounds__(256)
void softmax_rows(float* __restrict__ S) {
    S += (size_t)blockIdx.y * NNODE * NNODE;
    int row = blockIdx.x, tid = threadIdx.x;
    float2* r2 = (float2*)(S + (size_t)row * NNODE);
    __shared__ float red[256];

    float2 v[8];
    float mx = -3.4e38f;
#pragma unroll
    for (int j = 0; j < 8; j++) {
        v[j] = r2[tid + j * 256];
        mx = fmaxf(mx, fmaxf(v[j].x, v[j].y));
    }
    red[tid] = mx;
    __syncthreads();
    for (int s = 128; s > 0; s >>= 1) {
        if (tid < s) red[tid] = fmaxf(red[tid], red[tid + s]);
        __syncthreads();
    }
    mx = red[0];
    __syncthreads();

    float sum = 0.f;
#pragma unroll
    for (int j = 0; j < 8; j++) {
        v[j].x = __expf(v[j].x - mx);
        v[j].y = __expf(v[j].y - mx);
        sum += v[j].x + v[j].y;
    }
    red[tid] = sum;
    __syncthreads();
    for (int s = 128; s > 0; s >>= 1) {
        if (tid < s) red[tid] += red[tid + s];
        __syncthreads();
    }
    float inv = 1.f / red[0];
#pragma unroll
    for (int j = 0; j < 8; j++)
        r2[tid + j * 256] = make_float2(rtf32(v[j].x * inv), rtf32(v[j].y * inv));
}

// ---------------- GraphNorm statistics ---------------------------------------
__global__ void zero_stats() {
    int i = blockIdx.x * 256 + threadIdx.x;
    if (i < HRDIM) { g_sum[i] = 0.f; g_sqsum[i] = 0.f; g_normsq[i] = 0.f; }
}

__global__ __launch_bounds__(256)
void stats_kernel(const float* __restrict__ X) {
    int ch = blockIdx.x * 256 + threadIdx.x;
    int n0 = blockIdx.y * 512;
    float s = 0.f, s2 = 0.f;
    for (int n = n0; n < n0 + 512; n++) {
        float v = X[(size_t)n * HRDIM + ch];
        s += v;
        s2 += v * v;
    }
    atomicAdd(&g_sum[ch], s);
    atomicAdd(&g_sqsum[ch], s2);
}

__global__ void finalize_stats(const float* __restrict__ gw,
                               const float* __restrict__ gb,
                               const float* __restrict__ gms) {
    int j = blockIdx.x * 256 + threadIdx.x;
    if (j >= HRDIM) return;
    float m = g_sum[j] * (1.f / NNODE);
    float e2 = g_sqsum[j] * (1.f / NNODE);
    float s = gms[j];
    // var = E[o^2] - 2 s m E[o] + s^2 m^2
    float var = e2 - 2.f * s * m * m + s * s * m * m;
    float a = rsqrtf(var + 1e-5f) * gw[j];
    g_alpha[j] = a;
    g_beta[j] = gb[j] - s * m * a;
}

// normalize o -> gn (tf32-rounded), accumulate per-channel squared norms
__global__ __launch_bounds__(256)
void normalize_kernel(const float* __restrict__ X, float* __restrict__ Y) {
    int ch = blockIdx.x * 256 + threadIdx.x;
    int n0 = blockIdx.y * 512;
    float a = g_alpha[ch], b = g_beta[ch];
    float ns = 0.f;
    for (int n = n0; n < n0 + 512; n++) {
        size_t idx = (size_t)n * HRDIM + ch;
        float g = rtf32(X[idx] * a + b);
        Y[idx] = g;
        ns += g * g;
    }
    atomicAdd(&g_normsq[ch], ns);
}

// ---------------- launch ------------------------------------------------------
extern "C" void kernel_launch(void* const* d_in, const int* in_sizes, int n_in,
                              void* d_out, int out_size) {
    const float* lr_x = (const float*)d_in[0];
    const float* Wq = (const float*)d_in[1];
    const float* bq = (const float*)d_in[2];
    const float* Wk = (const float*)d_in[3];
    const float* bk = (const float*)d_in[4];
    const float* Wv = (const float*)d_in[5];
    const float* bv = (const float*)d_in[6];
    const float* Ws = (const float*)d_in[7];
    const float* bs = (const float*)d_in[8];
    const float* gw = (const float*)d_in[9];
    const float* gb = (const float*)d_in[10];
    const float* gms = (const float*)d_in[11];
    float* out = (float*)d_out;

    float *xT, *w4, *q, *k, *v, *o, *sc, *gn, *gnT, *nrm;
    cudaGetSymbolAddress((void**)&xT, g_xT);
    cudaGetSymbolAddress((void**)&w4, g_w4);
    cudaGetSymbolAddress((void**)&q, g_q);
    cudaGetSymbolAddress((void**)&k, g_k);
    cudaGetSymbolAddress((void**)&v, g_v);
    cudaGetSymbolAddress((void**)&o, g_o);
    cudaGetSymbolAddress((void**)&sc, g_scores);
    cudaGetSymbolAddress((void**)&gn, g_gn);
    cudaGetSymbolAddress((void**)&gnT, g_gnT);
    cudaGetSymbolAddress((void**)&nrm, g_normsq);

    const size_t WN = (size_t)LRDIM * HRDIM;
    const size_t SNN = (size_t)NNODE * NNODE;
    float* wq = w4;
    float* wk = w4 + WN;
    float* wv = w4 + 2 * WN;
    float* ws = w4 + 3 * WN;

    zero_stats<<<(HRDIM + 255) / 256, 256>>>();

    // prep: transpose+round x, round weights
    tconv_x_kernel<<<dim3(NNODE / 32, LRDIM / 32), dim3(32, 8)>>>(lr_x, xT);
    round_copy<<<(WN + 255) / 256, 256>>>(Wq, wq, WN);
    round_copy<<<(WN + 255) / 256, 256>>>(Wk, wk, WN);
    round_copy<<<(WN + 255) / 256, 256>>>(Wv, wv, WN);
    round_copy<<<(WN + 255) / 256, 256>>>(Ws, ws, WN);

    // projections: [4096,512] x [512,2048] (NN)
    dim3 gProj(HRDIM / 128, NNODE / 128, 1);
    tf32_gemm<0, 0><<<gProj, 128>>>(xT, wq, LRDIM, LRDIM, HRDIM, q, HRDIM, bq, 0.f, 0, 0, 0);
    tf32_gemm<0, 0><<<gProj, 128>>>(xT, wk, LRDIM, LRDIM, HRDIM, k, HRDIM, bk, 0.f, 0, 0, 0);
    tf32_gemm<0, 0><<<gProj, 128>>>(xT, wv, LRDIM, LRDIM, HRDIM, v, HRDIM, bv, 0.f, 0, 0, 0);
    tf32_gemm<0, 1><<<gProj, 128>>>(xT, ws, LRDIM, LRDIM, HRDIM, o, HRDIM, bs, 0.f, 0, 0, 0);

    const float scale = 1.f / sqrtf((float)CH);
    // batched scores over heads: scores[h] = scale * Qh @ Kh^T  (NT)
    dim3 gScore(NNODE / 128, NNODE / 128, NHEADS);
    tf32_gemm<1, 2><<<gScore, 128>>>(q, k, CH, HRDIM, HRDIM, sc, NNODE,
                                     nullptr, scale, CH, CH, SNN);
    // batched softmax over all heads
    softmax_rows<<<dim3(NNODE, NHEADS), 256>>>(sc);
    // batched AV: o[:, hCH:(h+1)CH] += attn[h] @ Vh  (NN)
    dim3 gAV(CH / 128, NNODE / 128, NHEADS);
    tf32_gemm<0, 3><<<gAV, 128>>>(sc, v, NNODE, NNODE, HRDIM, o, HRDIM,
                                  nullptr, 0.f, SNN, CH, CH);

    dim3 gStat(HRDIM / 256, NNODE / 512);
    stats_kernel<<<gStat, 256>>>(o);
    finalize_stats<<<(HRDIM + 255) / 256, 256>>>(gw, gb, gms);
    normalize_kernel<<<gStat, 256>>>(o, gn);
    tpose_kernel<<<dim3(HRDIM / 32, NNODE / 32), dim3(32, 8)>>>(gn, gnT);

    // gram: [2048,4096] x [4096,2048] (NN), normalized + relu
    dim3 gGram(HRDIM / 128, HRDIM / 128, 1);
    tf32_gemm<0, 4><<<gGram, 128>>>(gnT, gn, NNODE, NNODE, HRDIM,
                                    out, HRDIM, nrm, 0.f, 0, 0, 0);
}

// round 15
// speedup vs baseline: 6.1420x; 1.7788x over previous
#include <cuda_runtime.h>
#include <cuda_fp16.h>
#include <math.h>
#include <stdint.h>

#define LRDIM 512
#define HRDIM 2048
#define NNODE 4096
#define NHEADS 4
#define CH 512

typedef __half h16;
typedef __half2 h162;

// ---------------- scratch (device globals; no allocation allowed) -----------
__device__ h16 g_xh[(size_t)NNODE * LRDIM];         // lr_x^T, fp16
__device__ h16 g_wh[4][(size_t)LRDIM * HRDIM];      // Wq..Ws fp16
__device__ h16 g_q[(size_t)NNODE * HRDIM];
__device__ h16 g_k[(size_t)NNODE * HRDIM];
__device__ h16 g_v[(size_t)NNODE * HRDIM];
__device__ float g_o[(size_t)NNODE * HRDIM];
__device__ float g_scores[(size_t)NHEADS * NNODE * NNODE];
__device__ h16 g_attn[(size_t)NHEADS * NNODE * NNODE];
__device__ h16 g_gn[(size_t)NNODE * HRDIM];
__device__ h16 g_gnT[(size_t)HRDIM * NNODE];
__device__ float g_sum[HRDIM];
__device__ float g_sqsum[HRDIM];
__device__ float g_normsq[HRDIM];
__device__ float g_alpha[HRDIM];
__device__ float g_beta[HRDIM];

// ---------------- PTX helpers ------------------------------------------------
__device__ __forceinline__ uint32_t smem_u32(const void* p) {
    return (uint32_t)__cvta_generic_to_shared(p);
}
__device__ __forceinline__ void cp16(void* s, const void* g) {
    asm volatile("cp.async.cg.shared.global [%0], [%1], 16;\n"
                 :: "r"(smem_u32(s)), "l"(g));
}
__device__ __forceinline__ void cp_commit() {
    asm volatile("cp.async.commit_group;\n");
}
template <int N> __device__ __forceinline__ void cp_wait() {
    asm volatile("cp.async.wait_group %0;\n" :: "n"(N));
}
__device__ __forceinline__ void ldsm4(uint32_t& r0, uint32_t& r1, uint32_t& r2,
                                      uint32_t& r3, uint32_t a) {
    asm volatile("ldmatrix.sync.aligned.m8n8.x4.shared.b16 {%0,%1,%2,%3}, [%4];\n"
                 : "=r"(r0), "=r"(r1), "=r"(r2), "=r"(r3) : "r"(a));
}
__device__ __forceinline__ void ldsm4t(uint32_t& r0, uint32_t& r1, uint32_t& r2,
                                       uint32_t& r3, uint32_t a) {
    asm volatile("ldmatrix.sync.aligned.m8n8.x4.trans.shared.b16 {%0,%1,%2,%3}, [%4];\n"
                 : "=r"(r0), "=r"(r1), "=r"(r2), "=r"(r3) : "r"(a));
}
__device__ __forceinline__ void mma16816(float* c, const uint32_t* a, const uint32_t* b) {
    asm volatile(
        "mma.sync.aligned.m16n8k16.row.col.f32.f16.f16.f32 "
        "{%0,%1,%2,%3}, {%4,%5,%6,%7}, {%8,%9}, {%0,%1,%2,%3};\n"
        : "+f"(c[0]), "+f"(c[1]), "+f"(c[2]), "+f"(c[3])
        : "r"(a[0]), "r"(a[1]), "r"(a[2]), "r"(a[3]), "r"(b[0]), "r"(b[1]));
}

// ---------------- fp16 tensor-core GEMM --------------------------------------
// 128x128x32 CTA tile, 128 threads (4 warps), 64x64 warp tile.
// C[M,N] = A[M,K] (row-major fp16, lda) * B ; blockIdx.z batches via strides.
// BMODE 0 ("NN"): B row-major [K][N] (ldb)
// BMODE 1 ("NT"): B row-major [N][K] (ldb)  -> computes A * B^T
// EPI 0: +bias -> fp16 Ch    EPI 1: +bias -> f32 Cf
// EPI 2: *scale -> f32 Cf    EPI 3: Cf += acc
// EPI 4: gram normalize + relu -> f32 Cf (p1 = squared norms)
template <int BMODE, int EPI>
__global__ __launch_bounds__(128)
void h_gemm(const h16* __restrict__ A, const h16* __restrict__ B,
            int K, int lda, int ldb,
            float* __restrict__ Cf, h16* __restrict__ Ch, int ldc,
            const float* __restrict__ p1, float scale,
            size_t aHS, size_t bHS, size_t cHS) {
    constexpr int BM = 128, BN = 128, BK = 32;
    constexpr int BSR = (BMODE == 0) ? BK : BN;
    constexpr int BSC = (BMODE == 0) ? (BN + 8) : (BK + 8);
    __shared__ __align__(16) h16 As[2][BM][BK + 8];   // 80B rows (16B-mult)
    __shared__ __align__(16) h16 Bs[2][BSR][BSC];     // NN 272B, NT 80B rows

    A += (size_t)blockIdx.z * aHS;
    B += (size_t)blockIdx.z * bHS;
    if (EPI == 0) Ch += (size_t)blockIdx.z * cHS;
    else          Cf += (size_t)blockIdx.z * cHS;

    const int tid = threadIdx.x, lane = tid & 31, warp = tid >> 5;
    const int wm = warp >> 1, wn = warp & 1;        // 2x2 warps, 64x64 tiles
    const int m0 = blockIdx.y * BM, n0 = blockIdx.x * BN;

    float acc[4][8][4];
#pragma unroll
    for (int i = 0; i < 4; i++)
#pragma unroll
        for (int j = 0; j < 8; j++)
#pragma unroll
            for (int l = 0; l < 4; l++) acc[i][j][l] = 0.f;

    auto loadA = [&](int buf, int k0) {
#pragma unroll
        for (int r = 0; r < 4; r++) {
            int c = tid + 128 * r;               // 512 chunks = 128 x 4
            int row = c >> 2, ch = c & 3;
            cp16(&As[buf][row][ch * 8], A + (size_t)(m0 + row) * lda + k0 + ch * 8);
        }
    };
    auto loadB = [&](int buf, int k0) {
        if (BMODE == 0) {
#pragma unroll
            for (int r = 0; r < 4; r++) {
                int c = tid + 128 * r;           // 32 rows x 16 chunks
                int row = c >> 4, ch = c & 15;
                cp16(&Bs[buf][row][ch * 8], B + (size_t)(k0 + row) * ldb + n0 + ch * 8);
            }
        } else {
#pragma unroll
            for (int r = 0; r < 4; r++) {
                int c = tid + 128 * r;           // 128 rows x 4 chunks
                int row = c >> 2, ch = c & 3;
                cp16(&Bs[buf][row][ch * 8], B + (size_t)(n0 + row) * ldb + k0 + ch * 8);
            }
        }
    };

    loadA(0, 0); loadB(0, 0); cp_commit();
    int buf = 0;
    for (int k0 = 0; k0 < K; k0 += BK) {
        bool has_next = (k0 + BK < K);
        if (has_next) { loadA(buf ^ 1, k0 + BK); loadB(buf ^ 1, k0 + BK); cp_commit(); }
        if (has_next) cp_wait<1>(); else cp_wait<0>();
        __syncthreads();

#pragma unroll
        for (int kk = 0; kk < 2; kk++) {
            uint32_t a[4][4], b[8][2];
            const int ar = lane & 15, ac = kk * 16 + (lane >> 4) * 8;
#pragma unroll
            for (int mi = 0; mi < 4; mi++)
                ldsm4(a[mi][0], a[mi][1], a[mi][2], a[mi][3],
                      smem_u32(&As[buf][wm * 64 + mi * 16 + ar][ac]));

            if (BMODE == 0) {
#pragma unroll
                for (int nj = 0; nj < 4; nj++) {
                    uint32_t r0, r1, r2, r3;
                    ldsm4t(r0, r1, r2, r3,
                           smem_u32(&Bs[buf][kk * 16 + (lane & 15)]
                                       [wn * 64 + nj * 16 + (lane >> 4) * 8]));
                    b[2 * nj][0] = r0; b[2 * nj][1] = r1;
                    b[2 * nj + 1][0] = r2; b[2 * nj + 1][1] = r3;
                }
            } else {
#pragma unroll
                for (int nj = 0; nj < 4; nj++) {
                    uint32_t r0, r1, r2, r3;
                    ldsm4(r0, r1, r2, r3,
                          smem_u32(&Bs[buf][wn * 64 + nj * 16 + (lane & 15)]
                                      [kk * 16 + (lane >> 4) * 8]));
                    b[2 * nj][0] = r0; b[2 * nj][1] = r2;
                    b[2 * nj + 1][0] = r1; b[2 * nj + 1][1] = r3;
                }
            }
#pragma unroll
            for (int mi = 0; mi < 4; mi++)
#pragma unroll
                for (int ni = 0; ni < 8; ni++)
                    mma16816(acc[mi][ni], a[mi], b[ni]);
        }
        __syncthreads();
        buf ^= 1;
    }

    // epilogue: c0,c1 -> (row=group, col=2t,2t+1); c2,c3 -> row+8
    const int rb = lane >> 2, cb = (lane & 3) * 2;
#pragma unroll
    for (int mi = 0; mi < 4; mi++) {
#pragma unroll
        for (int half = 0; half < 2; half++) {
            int r = m0 + wm * 64 + mi * 16 + rb + half * 8;
            float rs_r = 0.f;
            if (EPI == 4) rs_r = rsqrtf(p1[r]);
#pragma unroll
            for (int ni = 0; ni < 8; ni++) {
                int col = n0 + wn * 64 + ni * 8 + cb;
                float v0 = acc[mi][ni][half * 2 + 0];
                float v1 = acc[mi][ni][half * 2 + 1];
                size_t idx = (size_t)r * ldc + col;
                if (EPI == 0) {
                    v0 += p1[col]; v1 += p1[col + 1];
                    *(h162*)(Ch + idx) = __floats2half2_rn(v0, v1);
                } else if (EPI == 1) {
                    *(float2*)(Cf + idx) = make_float2(v0 + p1[col], v1 + p1[col + 1]);
                } else if (EPI == 2) {
                    *(float2*)(Cf + idx) = make_float2(v0 * scale, v1 * scale);
                } else if (EPI == 3) {
                    float2 old = *(float2*)(Cf + idx);
                    *(float2*)(Cf + idx) = make_float2(old.x + v0, old.y + v1);
                } else {
                    v0 = fmaxf(v0 * rs_r * rsqrtf(p1[col]), 0.f);
                    v1 = fmaxf(v1 * rs_r * rsqrtf(p1[col + 1]), 0.f);
                    *(float2*)(Cf + idx) = make_float2(v0, v1);
                }
            }
        }
    }
}

// ---------------- prep kernels ------------------------------------------------
__global__ void f2h_kernel(const float* __restrict__ x, h16* __restrict__ y, int n) {
    int i = blockIdx.x * 256 + threadIdx.x;
    if (i < n) y[i] = __float2half_rn(x[i]);
}

// lr_x [LR][N] fp32 -> xh [N][LR] fp16
__global__ void tconv_x_kernel(const float* __restrict__ X, h16* __restrict__ Y) {
    __shared__ float t[32][33];
    int n0 = blockIdx.x * 32, k0 = blockIdx.y * 32;
    int tx = threadIdx.x, ty = threadIdx.y;
#pragma unroll
    for (int r = 0; r < 32; r += 8)
        t[ty + r][tx] = X[(size_t)(k0 + ty + r) * NNODE + n0 + tx];
    __syncthreads();
#pragma unroll
    for (int r = 0; r < 32; r += 8)
        Y[(size_t)(n0 + ty + r) * LRDIM + k0 + tx] = __float2half_rn(t[tx][ty + r]);
}

// gn [N][HR] fp16 -> gnT [HR][N] fp16
__global__ void tpose_h_kernel(const h16* __restrict__ X, h16* __restrict__ Y) {
    __shared__ h16 t[32][33];
    int c0 = blockIdx.x * 32, n0 = blockIdx.y * 32;
    int tx = threadIdx.x, ty = threadIdx.y;
#pragma unroll
    for (int r = 0; r < 32; r += 8)
        t[ty + r][tx] = X[(size_t)(n0 + ty + r) * HRDIM + c0 + tx];
    __syncthreads();
#pragma unroll
    for (int r = 0; r < 32; r += 8)
        Y[(size_t)(c0 + ty + r) * NNODE + n0 + tx] = t[tx][ty + r];
}

// ---------------- softmax: fp32 scores -> fp16 attn --------------------------
// grid (NNODE, NHEADS)
__global__ __launch_bounds__(256)
void softmax_h(const float* __restrict__ S, h16* __restrict__ P) {
    S += (size_t)blockIdx.y * NNODE * NNODE;
    P += (size_t)blockIdx.y * NNODE * NNODE;
    int row = blockIdx.x, tid = threadIdx.x;
    const float2* r2 = (const float2*)(S + (size_t)row * NNODE);
    h162* p2 = (h162*)(P + (size_t)row * NNODE);
    __shared__ float red[256];

    float2 v[8];
    float mx = -3.4e38f;
#pragma unroll
    for (int j = 0; j < 8; j++) {
        v[j] = r2[tid + j * 256];
        mx = fmaxf(mx, fmaxf(v[j].x, v[j].y));
    }
    red[tid] = mx;
    __syncthreads();
    for (int s = 128; s > 0; s >>= 1) {
        if (tid < s) red[tid] = fmaxf(red[tid], red[tid + s]);
        __syncthreads();
    }
    mx = red[0];
    __syncthreads();

    float sum = 0.f;
#pragma unroll
    for (int j = 0; j < 8; j++) {
        v[j].x = __expf(v[j].x - mx);
        v[j].y = __expf(v[j].y - mx);
        sum += v[j].x + v[j].y;
    }
    red[tid] = sum;
    __syncthreads();
    for (int s = 128; s > 0; s >>= 1) {
        if (tid < s) red[tid] += red[tid + s];
        __syncthreads();
    }
    float inv = 1.f / red[0];
#pragma unroll
    for (int j = 0; j < 8; j++)
        p2[tid + j * 256] = __floats2half2_rn(v[j].x * inv, v[j].y * inv);
}

// ---------------- GraphNorm statistics ---------------------------------------
__global__ void zero_stats() {
    int i = blockIdx.x * 256 + threadIdx.x;
    if (i < HRDIM) { g_sum[i] = 0.f; g_sqsum[i] = 0.f; g_normsq[i] = 0.f; }
}

__global__ __launch_bounds__(256)
void stats_kernel(const float* __restrict__ X) {
    int ch = blockIdx.x * 256 + threadIdx.x;
    int n0 = blockIdx.y * 512;
    float s = 0.f, s2 = 0.f;
    for (int n = n0; n < n0 + 512; n++) {
        float v = X[(size_t)n * HRDIM + ch];
        s += v;
        s2 += v * v;
    }
    atomicAdd(&g_sum[ch], s);
    atomicAdd(&g_sqsum[ch], s2);
}

__global__ void finalize_stats(const float* __restrict__ gw,
                               const float* __restrict__ gb,
                               const float* __restrict__ gms) {
    int j = blockIdx.x * 256 + threadIdx.x;
    if (j >= HRDIM) return;
    float m = g_sum[j] * (1.f / NNODE);
    float e2 = g_sqsum[j] * (1.f / NNODE);
    float s = gms[j];
    float var = e2 - 2.f * s * m * m + s * s * m * m;
    float a = rsqrtf(var + 1e-5f) * gw[j];
    g_alpha[j] = a;
    g_beta[j] = gb[j] - s * m * a;
}

// normalize o (fp32) -> gn (fp16); accumulate norms of the ROUNDED values
__global__ __launch_bounds__(256)
void normalize_h(const float* __restrict__ X, h16* __restrict__ Y) {
    int ch = blockIdx.x * 256 + threadIdx.x;
    int n0 = blockIdx.y * 512;
    float a = g_alpha[ch], b = g_beta[ch];
    float ns = 0.f;
    for (int n = n0; n < n0 + 512; n++) {
        size_t idx = (size_t)n * HRDIM + ch;
        h16 hv = __float2half_rn(X[idx] * a + b);
        Y[idx] = hv;
        float gf = __half2float(hv);
        ns += gf * gf;
    }
    atomicAdd(&g_normsq[ch], ns);
}

// ---------------- launch ------------------------------------------------------
extern "C" void kernel_launch(void* const* d_in, const int* in_sizes, int n_in,
                              void* d_out, int out_size) {
    const float* lr_x = (const float*)d_in[0];
    const float* Wq = (const float*)d_in[1];
    const float* bq = (const float*)d_in[2];
    const float* Wk = (const float*)d_in[3];
    const float* bk = (const float*)d_in[4];
    const float* Wv = (const float*)d_in[5];
    const float* bv = (const float*)d_in[6];
    const float* Ws = (const float*)d_in[7];
    const float* bs = (const float*)d_in[8];
    const float* gw = (const float*)d_in[9];
    const float* gb = (const float*)d_in[10];
    const float* gms = (const float*)d_in[11];
    float* out = (float*)d_out;

    h16 *xh, *wh, *q, *k, *v, *attn, *gn, *gnT;
    float *o, *sc, *nrm;
    cudaGetSymbolAddress((void**)&xh, g_xh);
    cudaGetSymbolAddress((void**)&wh, g_wh);
    cudaGetSymbolAddress((void**)&q, g_q);
    cudaGetSymbolAddress((void**)&k, g_k);
    cudaGetSymbolAddress((void**)&v, g_v);
    cudaGetSymbolAddress((void**)&attn, g_attn);
    cudaGetSymbolAddress((void**)&gn, g_gn);
    cudaGetSymbolAddress((void**)&gnT, g_gnT);
    cudaGetSymbolAddress((void**)&o, g_o);
    cudaGetSymbolAddress((void**)&sc, g_scores);
    cudaGetSymbolAddress((void**)&nrm, g_normsq);

    const size_t WN = (size_t)LRDIM * HRDIM;
    const size_t SNN = (size_t)NNODE * NNODE;
    h16* wq = wh;
    h16* wk = wh + WN;
    h16* wv = wh + 2 * WN;
    h16* ws = wh + 3 * WN;

    zero_stats<<<(HRDIM + 255) / 256, 256>>>();

    // prep: transpose+convert x, convert weights
    tconv_x_kernel<<<dim3(NNODE / 32, LRDIM / 32), dim3(32, 8)>>>(lr_x, xh);
    f2h_kernel<<<(WN + 255) / 256, 256>>>(Wq, wq, WN);
    f2h_kernel<<<(WN + 255) / 256, 256>>>(Wk, wk, WN);
    f2h_kernel<<<(WN + 255) / 256, 256>>>(Wv, wv, WN);
    f2h_kernel<<<(WN + 255) / 256, 256>>>(Ws, ws, WN);

    // projections: [4096,512] x [512,2048] (NN)
    dim3 gProj(HRDIM / 128, NNODE / 128, 1);
    h_gemm<0, 0><<<gProj, 128>>>(xh, wq, LRDIM, LRDIM, HRDIM, nullptr, q, HRDIM, bq, 0.f, 0, 0, 0);
    h_gemm<0, 0><<<gProj, 128>>>(xh, wk, LRDIM, LRDIM, HRDIM, nullptr, k, HRDIM, bk, 0.f, 0, 0, 0);
    h_gemm<0, 0><<<gProj, 128>>>(xh, wv, LRDIM, LRDIM, HRDIM, nullptr, v, HRDIM, bv, 0.f, 0, 0, 0);
    h_gemm<0, 1><<<gProj, 128>>>(xh, ws, LRDIM, LRDIM, HRDIM, o, nullptr, HRDIM, bs, 0.f, 0, 0, 0);

    const float scale = 1.f / sqrtf((float)CH);
    // batched scores over heads: scores[h] = scale * Qh @ Kh^T (NT)
    dim3 gScore(NNODE / 128, NNODE / 128, NHEADS);
    h_gemm<1, 2><<<gScore, 128>>>(q, k, CH, HRDIM, HRDIM, sc, nullptr, NNODE,
                                  nullptr, scale, CH, CH, SNN);
    softmax_h<<<dim3(NNODE, NHEADS), 256>>>(sc, attn);
    // batched AV: o[:, hCH:(h+1)CH] += attn[h] @ Vh (NN)
    dim3 gAV(CH / 128, NNODE / 128, NHEADS);
    h_gemm<0, 3><<<gAV, 128>>>(attn, v, NNODE, NNODE, HRDIM, o, nullptr, HRDIM,
                               nullptr, 0.f, SNN, CH, CH);

    dim3 gStat(HRDIM / 256, NNODE / 512);
    stats_kernel<<<gStat, 256>>>(o);
    finalize_stats<<<(HRDIM + 255) / 256, 256>>>(gw, gb, gms);
    normalize_h<<<gStat, 256>>>(o, gn);
    tpose_h_kernel<<<dim3(HRDIM / 32, NNODE / 32), dim3(32, 8)>>>(gn, gnT);

    // gram: gnT [HR][N] @ gn [N][HR] (NN), normalized + relu
    dim3 gGram(HRDIM / 128, HRDIM / 128, 1);
    h_gemm<0, 4><<<gGram, 128>>>(gnT, gn, NNODE, NNODE, HRDIM, out, nullptr,
                                 HRDIM, nrm, 0.f, 0, 0, 0);
}